// round 1
// baseline (speedup 1.0000x reference)
#include <cuda_runtime.h>

#define NT 256
#define NNODE 100
#define NEDGE 2000

struct SM {
    float bigA[10000];   // phase1: x [100,100]; phase2: xw2l|xw2r|h2pre|xw3|cg (5 x 2000)
    float bigB[6400];    // phase1: CSR scratch (with bigC); then xw_l; then Tx1|LhTx1|ass
    float bigC[6400];    // phase1: CSR scratch; then xw_r; then pooled|Hc|s2
    float h1[6400];      // [100,64]
    float h2[2000];      // [100,20]
    float ew[2000];
    float cl[2000];
    float cr[2000];
    int   src[2000];
    int   dst[2000];
    int   col[2000];     // edge ids sorted stably by dst
    int   rowptr[104];
    float dis_l[100], dis_r[100], dis_g[100], dis_c[100];
    float score[100], tanhv[64];
    int   node_idx[100], perm[64], ks[64];
    int   flag64;
};

__device__ __forceinline__ float lrelu(float v) { return v > 0.f ? v : 0.01f * v; }

__global__ __launch_bounds__(NT, 1) void brain_kernel(
    const float* __restrict__ x, const int* __restrict__ ei32, const float* __restrict__ ea,
    const float* __restrict__ Wl1, const float* __restrict__ bl1,
    const float* __restrict__ Wr1, const float* __restrict__ br1,
    const float* __restrict__ Wl2, const float* __restrict__ bl2,
    const float* __restrict__ Wr2, const float* __restrict__ br2,
    const float* __restrict__ Wg1, const float* __restrict__ bg1,
    const float* __restrict__ Wrel, const float* __restrict__ brel,
    const float* __restrict__ Wroot,
    const float* __restrict__ Wc0, const float* __restrict__ Wc1,
    const float* __restrict__ Wc2, const float* __restrict__ bc,
    float* __restrict__ out)
{
    extern __shared__ char raw[];
    SM* S = (SM*)raw;
    const int tid = threadIdx.x;

    // ---------- Phase 0: dtype probe + loads ----------
    if (tid == 0) S->flag64 = 0;
    __syncthreads();
    if (tid < 100) { if (ei32[2 * tid + 1] != 0) atomicOr(&S->flag64, 1); }
    for (int i = tid; i < 10000; i += NT) S->bigA[i] = x[i];
    for (int e = tid; e < NEDGE; e += NT) S->ew[e] = ea[e];
    __syncthreads();
    if (S->flag64 == 0) {   // int64 edge_index
        const long long* ei = (const long long*)ei32;
        for (int e = tid; e < NEDGE; e += NT) {
            S->src[e] = (int)ei[e];
            S->dst[e] = (int)ei[NEDGE + e];
        }
    } else {                // int32 edge_index
        for (int e = tid; e < NEDGE; e += NT) {
            S->src[e] = ei32[e];
            S->dst[e] = ei32[NEDGE + e];
        }
    }
    __syncthreads();

    // ---------- Phase 1: stable CSR by dst (chunked counting sort, deterministic) ----------
    int* cnt = (int*)S->bigB;   // 128*100 ints spans bigB+bigC
    if (tid < 128) {
        int* row = cnt + tid * 100;
        for (int d = 0; d < 100; d++) row[d] = 0;
        int e0 = tid * 16, e1 = min(e0 + 16, NEDGE);
        for (int e = e0; e < e1; e++) row[S->dst[e]]++;
    }
    __syncthreads();
    if (tid < 100) {
        int s = 0;
        for (int t = 0; t < 128; t++) { int v = cnt[t * 100 + tid]; cnt[t * 100 + tid] = s; s += v; }
        S->rowptr[tid + 1] = s;
    }
    __syncthreads();
    if (tid == 0) {
        S->rowptr[0] = 0;
        for (int i = 0; i < 100; i++) S->rowptr[i + 1] += S->rowptr[i];
    }
    __syncthreads();
    if (tid < 128) {
        int e0 = tid * 16, e1 = min(e0 + 16, NEDGE);
        int* row = cnt + tid * 100;
        for (int e = e0; e < e1; e++) {
            int d = S->dst[e];
            S->col[S->rowptr[d] + row[d]] = e;
            row[d]++;
        }
    }
    __syncthreads();

    // ---------- Phase 2: degrees / normalizers ----------
    if (tid < 100) {
        float dl = 0.f, dr = 0.f, dg = 0.f;
        int d = tid;
        for (int p = S->rowptr[d]; p < S->rowptr[d + 1]; p++) {
            int e = S->col[p]; int s = S->src[e]; float w = S->ew[e];
            dg += w;
            if (d < 50 && s < 50)   dl += w;
            if (d >= 50 && s >= 50) dr += w;
        }
        S->dis_l[d] = rsqrtf(dl + 1.f);
        S->dis_r[d] = rsqrtf(dr + 1.f);
        S->dis_g[d] = rsqrtf(dg + 1.f);
    }
    __syncthreads();
    for (int e = tid; e < NEDGE; e += NT) {
        int s = S->src[e], d = S->dst[e]; float w = S->ew[e];
        float wl = (s < 50 && d < 50) ? w : 0.f;
        float wr = (s >= 50 && d >= 50) ? w : 0.f;
        S->cl[e] = S->dis_l[s] * wl * S->dis_l[d];
        S->cr[e] = S->dis_r[s] * wr * S->dis_r[d];
    }
    __syncthreads();

    // ---------- Phase 3: layer-1 matmuls  xw_l = x@Wl1, xw_r = x@Wr1 ----------
    {
        const int j = tid & 63, ig = tid >> 6;   // j: out col, ig: row group base
        float accL[25], accR[25];
        #pragma unroll
        for (int r = 0; r < 25; r++) { accL[r] = 0.f; accR[r] = 0.f; }
        for (int k = 0; k < 100; k++) {
            float wl = __ldg(&Wl1[k * 64 + j]);
            float wr = __ldg(&Wr1[k * 64 + j]);
            #pragma unroll
            for (int r = 0; r < 25; r++) {
                float xv = S->bigA[(ig + 4 * r) * 100 + k];
                accL[r] += xv * wl;
                accR[r] += xv * wr;
            }
        }
        #pragma unroll
        for (int r = 0; r < 25; r++) {
            S->bigB[(ig + 4 * r) * 64 + j] = accL[r];
            S->bigC[(ig + 4 * r) * 64 + j] = accR[r];
        }
    }
    __syncthreads();

    // ---------- Phase 4: layer-1 GCN aggregate -> h1 ----------
    for (int idx = tid; idx < 6400; idx += NT) {
        int i = idx >> 6, f = idx & 63;
        const float* xw; const float* c; float di, bias;
        if (i < 50) { xw = S->bigB; c = S->cl; di = S->dis_l[i]; bias = __ldg(&bl1[f]); }
        else        { xw = S->bigC; c = S->cr; di = S->dis_r[i]; bias = __ldg(&br1[f]); }
        float acc = di * di * xw[i * 64 + f] + bias;
        for (int p = S->rowptr[i]; p < S->rowptr[i + 1]; p++) {
            int e = S->col[p];
            acc += c[e] * xw[S->src[e] * 64 + f];
        }
        S->h1[idx] = lrelu(acc);
    }
    __syncthreads();

    // ---------- Phase 5: layer-2 matmuls + global-edge coeffs ----------
    float* xw2l = S->bigA;          // [100,20]
    float* xw2r = S->bigA + 2000;
    float* h2p  = S->bigA + 4000;
    float* xw3  = S->bigA + 6000;
    float* cg   = S->bigA + 8000;
    for (int idx = tid; idx < 2000; idx += NT) {
        int i = idx / 20, f = idx % 20;
        float al = 0.f, ar = 0.f;
        for (int k = 0; k < 64; k++) {
            float hv = S->h1[i * 64 + k];
            al += hv * __ldg(&Wl2[k * 20 + f]);
            ar += hv * __ldg(&Wr2[k * 20 + f]);
        }
        xw2l[idx] = al; xw2r[idx] = ar;
    }
    for (int e = tid; e < NEDGE; e += NT)
        cg[e] = S->dis_g[S->src[e]] * S->ew[e] * S->dis_g[S->dst[e]];
    __syncthreads();

    // ---------- Phase 6: layer-2 GCN aggregate -> h2pre ----------
    for (int idx = tid; idx < 2000; idx += NT) {
        int i = idx / 20, f = idx % 20;
        const float* xw = (i < 50) ? xw2l : xw2r;
        const float* c  = (i < 50) ? S->cl : S->cr;
        float di   = (i < 50) ? S->dis_l[i] : S->dis_r[i];
        float bias = (i < 50) ? __ldg(&bl2[f]) : __ldg(&br2[f]);
        float acc = di * di * xw[i * 20 + f] + bias;
        for (int p = S->rowptr[i]; p < S->rowptr[i + 1]; p++) {
            int e = S->col[p];
            acc += c[e] * xw[S->src[e] * 20 + f];
        }
        h2p[idx] = lrelu(acc);
    }
    __syncthreads();

    // ---------- Phase 7: layer-3 GCN (full graph) -> h2 ----------
    for (int idx = tid; idx < 2000; idx += NT) {
        int i = idx / 20, f = idx % 20;
        float acc = 0.f;
        for (int k = 0; k < 20; k++) acc += h2p[i * 20 + k] * __ldg(&Wg1[k * 20 + f]);
        xw3[idx] = acc;
    }
    __syncthreads();
    for (int idx = tid; idx < 2000; idx += NT) {
        int i = idx / 20, f = idx % 20;
        float di = S->dis_g[i];
        float acc = di * di * xw3[i * 20 + f] + __ldg(&bg1[f]);
        for (int p = S->rowptr[i]; p < S->rowptr[i + 1]; p++) {
            int e = S->col[p];
            acc += cg[e] * xw3[S->src[e] * 20 + f];
        }
        S->h2[idx] = lrelu(acc);
    }
    __syncthreads();

    // ---------- Phase 8: SAGPool score ----------
    if (tid < 100) {
        int i = tid;
        float a[20];
        #pragma unroll
        for (int f = 0; f < 20; f++) a[f] = 0.f;
        for (int p = S->rowptr[i]; p < S->rowptr[i + 1]; p++) {
            int s = S->src[S->col[p]];
            #pragma unroll
            for (int f = 0; f < 20; f++) a[f] += S->h2[s * 20 + f];
        }
        float acc = __ldg(&brel[0]);
        #pragma unroll
        for (int f = 0; f < 20; f++)
            acc += a[f] * __ldg(&Wrel[f]) + S->h2[i * 20 + f] * __ldg(&Wroot[f]);
        S->score[i] = acc;
    }
    __syncthreads();

    // ---------- Phase 9: top-k(50) via rank counting (matches lax.top_k ties) ----------
    if (tid < 100) {
        float si = S->score[tid];
        int r = 0;
        for (int j = 0; j < 100; j++) {
            float sj = S->score[j];
            if (sj > si || (sj == si && j < tid)) r++;
        }
        S->node_idx[tid] = (r < 50) ? r : -1;
        if (r < 50) { S->perm[r] = tid; S->tanhv[r] = tanhf(si); }
    }
    __syncthreads();

    // ---------- Phase 10: ks (sorted kept ids), dis_c, pooled ----------
    if (tid < 100) {
        int r = S->node_idx[tid];
        if (r >= 0) {
            int pos = 0;
            for (int j = 0; j < tid; j++) if (S->node_idx[j] >= 0) pos++;
            S->ks[pos] = tid;
            float d = 0.f;
            for (int p = S->rowptr[tid]; p < S->rowptr[tid + 1]; p++)
                if (S->node_idx[S->src[S->col[p]]] >= 0) d += 1.f;
            S->dis_c[r] = (d > 0.f) ? rsqrtf(d) : 0.f;
        }
    }
    float* pooled = S->bigC;          // 1000
    float* Hc     = S->bigC + 1000;   // 400
    float* s2     = S->bigC + 1400;   // 2000
    for (int idx = tid; idx < 1000; idx += NT) {
        int r = idx / 20, f = idx % 20;
        pooled[idx] = S->h2[S->perm[r] * 20 + f] * S->tanhv[r];
    }
    __syncthreads();

    // ---------- Phase 11: Chebyshev Tx1 = Lhat(h2), LhTx1 = Lhat(Tx1) ----------
    float* Tx1 = S->bigB;
    float* Lh2 = S->bigB + 2000;
    float* ass = S->bigB + 4000;
    for (int idx = tid; idx < 2000; idx += NT) {
        int rr = idx / 20, f = idx % 20;
        float acc = 0.f;
        if (rr < 50) {
            int i = S->perm[rr];
            float dd = S->dis_c[rr];
            for (int p = S->rowptr[i]; p < S->rowptr[i + 1]; p++) {
                int rs = S->node_idx[S->src[S->col[p]]];
                if (rs >= 0) acc -= S->dis_c[rs] * dd * S->h2[rs * 20 + f];
            }
        }
        Tx1[idx] = acc;
    }
    __syncthreads();
    for (int idx = tid; idx < 2000; idx += NT) {
        int rr = idx / 20, f = idx % 20;
        float acc = 0.f;
        if (rr < 50) {
            int i = S->perm[rr];
            float dd = S->dis_c[rr];
            for (int p = S->rowptr[i]; p < S->rowptr[i + 1]; p++) {
                int rs = S->node_idx[S->src[S->col[p]]];
                if (rs >= 0) acc -= S->dis_c[rs] * dd * Tx1[rs * 20 + f];
            }
        }
        Lh2[idx] = acc;
    }
    __syncthreads();

    // ---------- Phase 12: s_raw = Tx0@Wc0 + Tx1@Wc1 + Tx2@Wc2 + bc ----------
    for (int idx = tid; idx < 2000; idx += NT) {
        int i = idx / 20, f = idx % 20;
        float acc = __ldg(&bc[f]);
        for (int k = 0; k < 20; k++) {
            float t0 = S->h2[i * 20 + k];
            float t1 = Tx1[i * 20 + k];
            float t2 = 2.f * Lh2[i * 20 + k] - t0;
            acc += t0 * __ldg(&Wc0[k * 20 + f])
                 + t1 * __ldg(&Wc1[k * 20 + f])
                 + t2 * __ldg(&Wc2[k * 20 + f]);
        }
        ass[idx] = acc;  // holds s_raw for now
    }
    __syncthreads();

    // ---------- Phase 13: double softmax ----------
    if (tid < 100) {
        float v[20];
        float m = -1e30f;
        for (int f = 0; f < 20; f++) { v[f] = ass[tid * 20 + f]; m = fmaxf(m, v[f]); }
        float sum = 0.f;
        for (int f = 0; f < 20; f++) { v[f] = expf(v[f] - m); sum += v[f]; }
        float inv = 1.f / sum;
        float m2 = -1e30f;
        for (int f = 0; f < 20; f++) { v[f] *= inv; ass[tid * 20 + f] = v[f]; m2 = fmaxf(m2, v[f]); }
        float w[20]; float s2sum = 0.f;
        for (int f = 0; f < 20; f++) { w[f] = expf(v[f] - m2); s2sum += w[f]; }
        float inv2 = 1.f / s2sum;
        for (int f = 0; f < 20; f++) s2[tid * 20 + f] = w[f] * inv2;
    }
    __syncthreads();

    // ---------- Phase 14: H_coarse = s2^T @ h2 ----------
    for (int idx = tid; idx < 400; idx += NT) {
        int c = idx / 20, f = idx % 20;
        float acc = 0.f;
        for (int i = 0; i < 100; i++) acc += s2[i * 20 + c] * S->h2[i * 20 + f];
        Hc[idx] = acc;
    }
    __syncthreads();

    // ---------- Phase 15: out = pooled + ass[sorted(perm)] @ H_coarse ----------
    for (int idx = tid; idx < 1000; idx += NT) {
        int j = idx / 20, f = idx % 20;
        float acc = pooled[idx];
        int row = S->ks[j];
        for (int c = 0; c < 20; c++) acc += ass[row * 20 + c] * Hc[c * 20 + f];
        out[idx] = acc;
    }
}

extern "C" void kernel_launch(void* const* d_in, const int* in_sizes, int n_in,
                              void* d_out, int out_size)
{
    (void)in_sizes; (void)n_in; (void)out_size;
    const float* x    = (const float*)d_in[0];
    const int*   ei   = (const int*)d_in[1];   // probed for int32 vs int64 in-kernel
    const float* ea   = (const float*)d_in[2];
    // d_in[3] = adj (unused by reference)
    const float* Wl1  = (const float*)d_in[4];
    const float* bl1  = (const float*)d_in[5];
    const float* Wr1  = (const float*)d_in[6];
    const float* br1  = (const float*)d_in[7];
    const float* Wl2  = (const float*)d_in[8];
    const float* bl2  = (const float*)d_in[9];
    const float* Wr2  = (const float*)d_in[10];
    const float* br2  = (const float*)d_in[11];
    const float* Wg1  = (const float*)d_in[12];
    const float* bg1  = (const float*)d_in[13];
    const float* Wrel = (const float*)d_in[14];
    const float* brel = (const float*)d_in[15];
    const float* Wroot= (const float*)d_in[16];
    const float* Wc0  = (const float*)d_in[17];
    const float* Wc1  = (const float*)d_in[18];
    const float* Wc2  = (const float*)d_in[19];
    const float* bc   = (const float*)d_in[20];

    size_t smem = sizeof(SM);
    cudaFuncSetAttribute(brain_kernel, cudaFuncAttributeMaxDynamicSharedMemorySize, (int)smem);
    brain_kernel<<<1, NT, smem>>>(x, ei, ea, Wl1, bl1, Wr1, br1, Wl2, bl2, Wr2, br2,
                                  Wg1, bg1, Wrel, brel, Wroot, Wc0, Wc1, Wc2, bc,
                                  (float*)d_out);
}

// round 2
// speedup vs baseline: 1.6687x; 1.6687x over previous
#include <cuda_runtime.h>

#define NT 1024
#define NEDGE 2000

__device__ float g_xwl[6400];
__device__ float g_xwr[6400];

struct SM {
    float bigA[10000];   // CSR cnt (int alias, 100x100) -> xw2l|xw2r|h2p|xw3|scratch
    float bigB[6400];    // xwl ; later Tx1|Lh2|ass
    float bigC[6400];    // xwr ; later pooled|Hc|s2
    float h1[6400];
    float h2[2000];
    float ew[2000];
    float csr_w[2000];
    float ccl[2000];     // later ccheb
    float ccr[2000];
    float ccg[2000];
    int   src[2000];     // later remsrc
    int   dst[2000];
    int   col[2000];
    int   csr_src[2000];
    int   csr_dst[2000];
    int   rowptr[104];
    int   scanbuf[128];
    float dis_l[100], dis_r[100], dis_g[100], dis_c[100];
    float score[100], tanhv[64];
    int   node_idx[100], perm[64], ks[64];
    int   flag64;
};

__device__ __forceinline__ float lrelu(float v) { return v > 0.f ? v : 0.01f * v; }

// ---------------- K1: layer-1 matmuls across 25 SMs ----------------
__global__ __launch_bounds__(256, 1) void mm1_kernel(
    const float* __restrict__ x,
    const float* __restrict__ Wl1, const float* __restrict__ Wr1)
{
    __shared__ float xs[400];
    const int b = blockIdx.x, tid = threadIdx.x;
    for (int i = tid; i < 400; i += 256) xs[i] = x[b * 400 + i];
    __syncthreads();
    const int j = tid & 63, r = tid >> 6;
    float al = 0.f, ar = 0.f;
    for (int k = 0; k < 100; k++) {
        float xv = xs[r * 100 + k];
        al += xv * __ldg(&Wl1[k * 64 + j]);
        ar += xv * __ldg(&Wr1[k * 64 + j]);
    }
    const int row = b * 4 + r;
    g_xwl[row * 64 + j] = al;
    g_xwr[row * 64 + j] = ar;
}

// ---------------- K2: everything else, one block, 1024 threads ----------------
__global__ __launch_bounds__(NT, 1) void brain_kernel(
    const int* __restrict__ ei32, const float* __restrict__ ea,
    const float* __restrict__ bl1, const float* __restrict__ br1,
    const float* __restrict__ Wl2, const float* __restrict__ bl2,
    const float* __restrict__ Wr2, const float* __restrict__ br2,
    const float* __restrict__ Wg1, const float* __restrict__ bg1,
    const float* __restrict__ Wrel, const float* __restrict__ brel,
    const float* __restrict__ Wroot,
    const float* __restrict__ Wc0, const float* __restrict__ Wc1,
    const float* __restrict__ Wc2, const float* __restrict__ bc,
    float* __restrict__ out)
{
    extern __shared__ char raw[];
    SM* S = (SM*)raw;
    const int tid = threadIdx.x;

    // ---- Phase 0: dtype probe + edge loads + stage layer-1 matmul results ----
    if (tid == 0) S->flag64 = 0;
    __syncthreads();
    if (tid < 100) { if (ei32[2 * tid + 1] != 0) atomicOr(&S->flag64, 1); }
    for (int e = tid; e < NEDGE; e += NT) S->ew[e] = ea[e];
    for (int i = tid; i < 6400; i += NT) { S->bigB[i] = g_xwl[i]; S->bigC[i] = g_xwr[i]; }
    __syncthreads();
    if (S->flag64 == 0) {
        const long long* ei = (const long long*)ei32;
        for (int e = tid; e < NEDGE; e += NT) {
            S->src[e] = (int)ei[e];
            S->dst[e] = (int)ei[NEDGE + e];
        }
    } else {
        for (int e = tid; e < NEDGE; e += NT) {
            S->src[e] = ei32[e];
            S->dst[e] = ei32[NEDGE + e];
        }
    }
    __syncthreads();

    // ---- Phase 1: stable CSR by dst (100 chunks of 20, deterministic) ----
    int* cnt = (int*)S->bigA;   // 100*100 ints = 40KB
    if (tid < 100) {
        int* row = cnt + tid * 100;
        for (int d = 0; d < 100; d++) row[d] = 0;
        const int e0 = tid * 20;
        for (int e = e0; e < e0 + 20; e++) row[S->dst[e]]++;
    }
    __syncthreads();
    int myTotal = 0;
    if (tid < 100) {
        int s = 0;
        for (int t = 0; t < 100; t++) { int v = cnt[t * 100 + tid]; cnt[t * 100 + tid] = s; s += v; }
        myTotal = s;
    }
    if (tid < 128) S->scanbuf[tid] = (tid < 100) ? myTotal : 0;
    __syncthreads();
    // inclusive Hillis-Steele scan over 128
    #pragma unroll
    for (int off = 1; off < 128; off <<= 1) {
        int add = 0;
        if (tid < 128 && tid >= off) add = S->scanbuf[tid - off];
        __syncthreads();
        if (tid < 128) S->scanbuf[tid] += add;
        __syncthreads();
    }
    if (tid < 100) S->rowptr[tid + 1] = S->scanbuf[tid];
    if (tid == 0) S->rowptr[0] = 0;
    __syncthreads();
    if (tid < 100) {
        const int e0 = tid * 20;
        int* row = cnt + tid * 100;
        for (int e = e0; e < e0 + 20; e++) {
            int d = S->dst[e];
            S->col[S->rowptr[d] + row[d]] = e;
            row[d]++;
        }
    }
    __syncthreads();

    // ---- Phase 1.5: gather edge data into CSR order ----
    for (int p = tid; p < NEDGE; p += NT) {
        int e = S->col[p];
        S->csr_src[p] = S->src[e];
        S->csr_dst[p] = S->dst[e];
        S->csr_w[p]   = S->ew[e];
    }
    __syncthreads();

    // ---- Phase 2: degrees / coefficients ----
    if (tid < 100) {
        float dl = 0.f, dr = 0.f, dg = 0.f;
        const int d = tid;
        for (int p = S->rowptr[d]; p < S->rowptr[d + 1]; p++) {
            int s = S->csr_src[p]; float w = S->csr_w[p];
            dg += w;
            if (d < 50 && s < 50)   dl += w;
            if (d >= 50 && s >= 50) dr += w;
        }
        S->dis_l[d] = rsqrtf(dl + 1.f);
        S->dis_r[d] = rsqrtf(dr + 1.f);
        S->dis_g[d] = rsqrtf(dg + 1.f);
    }
    __syncthreads();
    for (int p = tid; p < NEDGE; p += NT) {
        int s = S->csr_src[p], d = S->csr_dst[p]; float w = S->csr_w[p];
        S->ccl[p] = (s < 50 && d < 50)   ? S->dis_l[s] * w * S->dis_l[d] : 0.f;
        S->ccr[p] = (s >= 50 && d >= 50) ? S->dis_r[s] * w * S->dis_r[d] : 0.f;
        S->ccg[p] = S->dis_g[s] * w * S->dis_g[d];
    }
    __syncthreads();

    // ---- Phase 4: layer-1 GCN aggregate -> h1 ----
    for (int idx = tid; idx < 6400; idx += NT) {
        int i = idx >> 6, f = idx & 63;
        const float* xw; const float* c; float di, bias;
        if (i < 50) { xw = S->bigB; c = S->ccl; di = S->dis_l[i]; bias = __ldg(&bl1[f]); }
        else        { xw = S->bigC; c = S->ccr; di = S->dis_r[i]; bias = __ldg(&br1[f]); }
        float acc = di * di * xw[i * 64 + f] + bias;
        for (int p = S->rowptr[i]; p < S->rowptr[i + 1]; p++)
            acc += c[p] * xw[S->csr_src[p] * 64 + f];
        S->h1[idx] = lrelu(acc);
    }
    __syncthreads();

    // ---- Phase 5: layer-2 matmuls ----
    float* xw2l = S->bigA;
    float* xw2r = S->bigA + 2000;
    float* h2p  = S->bigA + 4000;
    float* xw3  = S->bigA + 6000;
    float* tmp  = S->bigA + 8000;
    for (int idx = tid; idx < 2000; idx += NT) {
        int i = idx / 20, f = idx % 20;
        float al = 0.f, ar = 0.f;
        for (int k = 0; k < 64; k++) {
            float hv = S->h1[i * 64 + k];
            al += hv * __ldg(&Wl2[k * 20 + f]);
            ar += hv * __ldg(&Wr2[k * 20 + f]);
        }
        xw2l[idx] = al; xw2r[idx] = ar;
    }
    __syncthreads();

    // ---- Phase 6: layer-2 GCN aggregate ----
    for (int idx = tid; idx < 2000; idx += NT) {
        int i = idx / 20, f = idx % 20;
        const float* xw = (i < 50) ? xw2l : xw2r;
        const float* c  = (i < 50) ? S->ccl : S->ccr;
        float di   = (i < 50) ? S->dis_l[i] : S->dis_r[i];
        float bias = (i < 50) ? __ldg(&bl2[f]) : __ldg(&br2[f]);
        float acc = di * di * xw[i * 20 + f] + bias;
        for (int p = S->rowptr[i]; p < S->rowptr[i + 1]; p++)
            acc += c[p] * xw[S->csr_src[p] * 20 + f];
        h2p[idx] = lrelu(acc);
    }
    __syncthreads();

    // ---- Phase 7: layer-3 GCN (full graph) -> h2 ----
    for (int idx = tid; idx < 2000; idx += NT) {
        int i = idx / 20, f = idx % 20;
        float acc = 0.f;
        for (int k = 0; k < 20; k++) acc += h2p[i * 20 + k] * __ldg(&Wg1[k * 20 + f]);
        xw3[idx] = acc;
    }
    __syncthreads();
    for (int idx = tid; idx < 2000; idx += NT) {
        int i = idx / 20, f = idx % 20;
        float di = S->dis_g[i];
        float acc = di * di * xw3[i * 20 + f] + __ldg(&bg1[f]);
        for (int p = S->rowptr[i]; p < S->rowptr[i + 1]; p++)
            acc += S->ccg[p] * xw3[S->csr_src[p] * 20 + f];
        S->h2[idx] = lrelu(acc);
    }
    __syncthreads();

    // ---- Phase 8: SAGPool score ----
    for (int idx = tid; idx < 2000; idx += NT) {
        int i = idx / 20, f = idx % 20;
        float acc = 0.f;
        for (int p = S->rowptr[i]; p < S->rowptr[i + 1]; p++)
            acc += S->h2[S->csr_src[p] * 20 + f];
        tmp[idx] = acc;
    }
    __syncthreads();
    if (tid < 100) {
        float acc = __ldg(&brel[0]);
        for (int f = 0; f < 20; f++)
            acc += tmp[tid * 20 + f] * __ldg(&Wrel[f]) + S->h2[tid * 20 + f] * __ldg(&Wroot[f]);
        S->score[tid] = acc;
    }
    __syncthreads();

    // ---- Phase 9: top-k(50) via rank counting ----
    if (tid < 100) {
        float si = S->score[tid];
        int r = 0;
        for (int j = 0; j < 100; j++) {
            float sj = S->score[j];
            if (sj > si || (sj == si && j < tid)) r++;
        }
        S->node_idx[tid] = (r < 50) ? r : -1;
        if (r < 50) { S->perm[r] = tid; S->tanhv[r] = tanhf(si); }
    }
    __syncthreads();

    // ---- Phase 10: ks, dis_c, pooled ----
    if (tid < 100) {
        int r = S->node_idx[tid];
        if (r >= 0) {
            int pos = 0;
            for (int j = 0; j < tid; j++) if (S->node_idx[j] >= 0) pos++;
            S->ks[pos] = tid;
            float d = 0.f;
            for (int p = S->rowptr[tid]; p < S->rowptr[tid + 1]; p++)
                if (S->node_idx[S->csr_src[p]] >= 0) d += 1.f;
            S->dis_c[r] = (d > 0.f) ? rsqrtf(d) : 0.f;
        }
    }
    float* pooled = S->bigC;
    float* Hc     = S->bigC + 1000;
    float* s2     = S->bigC + 1400;
    for (int idx = tid; idx < 1000; idx += NT) {
        int r = idx / 20, f = idx % 20;
        pooled[idx] = S->h2[S->perm[r] * 20 + f] * S->tanhv[r];
    }
    __syncthreads();

    // ---- Phase 10.5: Chebyshev per-edge coeff + remapped source ----
    float* ccheb = S->ccl;           // alias (ccl dead)
    int*   remsrc = S->src;          // alias (src dead)
    for (int p = tid; p < NEDGE; p += NT) {
        int rs = S->node_idx[S->csr_src[p]];
        int rd = S->node_idx[S->csr_dst[p]];
        if (rs >= 0 && rd >= 0) {
            ccheb[p] = -S->dis_c[rs] * S->dis_c[rd];
            remsrc[p] = rs * 20;
        } else { ccheb[p] = 0.f; remsrc[p] = 0; }
    }
    __syncthreads();

    // ---- Phase 11: Tx1 = Lhat(h2), Lh2 = Lhat(Tx1) ----
    float* Tx1 = S->bigB;
    float* Lh2 = S->bigB + 2000;
    float* ass = S->bigB + 4000;
    for (int idx = tid; idx < 2000; idx += NT) {
        int rr = idx / 20, f = idx % 20;
        float acc = 0.f;
        if (rr < 50) {
            int i = S->perm[rr];
            for (int p = S->rowptr[i]; p < S->rowptr[i + 1]; p++)
                acc += ccheb[p] * S->h2[remsrc[p] + f];
        }
        Tx1[idx] = acc;
    }
    __syncthreads();
    for (int idx = tid; idx < 2000; idx += NT) {
        int rr = idx / 20, f = idx % 20;
        float acc = 0.f;
        if (rr < 50) {
            int i = S->perm[rr];
            for (int p = S->rowptr[i]; p < S->rowptr[i + 1]; p++)
                acc += ccheb[p] * Tx1[remsrc[p] + f];
        }
        Lh2[idx] = acc;
    }
    __syncthreads();

    // ---- Phase 12: s_raw ----
    for (int idx = tid; idx < 2000; idx += NT) {
        int i = idx / 20, f = idx % 20;
        float acc = __ldg(&bc[f]);
        for (int k = 0; k < 20; k++) {
            float t0 = S->h2[i * 20 + k];
            float t1 = Tx1[i * 20 + k];
            float t2 = 2.f * Lh2[i * 20 + k] - t0;
            acc += t0 * __ldg(&Wc0[k * 20 + f])
                 + t1 * __ldg(&Wc1[k * 20 + f])
                 + t2 * __ldg(&Wc2[k * 20 + f]);
        }
        ass[idx] = acc;
    }
    __syncthreads();

    // ---- Phase 13: double softmax (array-free) ----
    for (int pass = 0; pass < 2; pass++) {
        float* dstbuf = (pass == 0) ? ass : s2;
        for (int idx = tid; idx < 2000; idx += NT) {
            int i = idx / 20;
            float m = -1e30f;
            for (int k = 0; k < 20; k++) m = fmaxf(m, ass[i * 20 + k]);
            tmp[idx] = expf(ass[idx] - m);
        }
        __syncthreads();
        for (int idx = tid; idx < 2000; idx += NT) {
            int i = idx / 20;
            float s = 0.f;
            for (int k = 0; k < 20; k++) s += tmp[i * 20 + k];
            dstbuf[idx] = tmp[idx] / s;
        }
        __syncthreads();
    }

    // ---- Phase 14: H_coarse = s2^T @ h2 ----
    for (int idx = tid; idx < 400; idx += NT) {
        int c = idx / 20, f = idx % 20;
        float acc = 0.f;
        for (int i = 0; i < 100; i++) acc += s2[i * 20 + c] * S->h2[i * 20 + f];
        Hc[idx] = acc;
    }
    __syncthreads();

    // ---- Phase 15: out ----
    for (int idx = tid; idx < 1000; idx += NT) {
        int j = idx / 20, f = idx % 20;
        float acc = pooled[idx];
        int row = S->ks[j];
        for (int c = 0; c < 20; c++) acc += ass[row * 20 + c] * Hc[c * 20 + f];
        out[idx] = acc;
    }
}

extern "C" void kernel_launch(void* const* d_in, const int* in_sizes, int n_in,
                              void* d_out, int out_size)
{
    (void)in_sizes; (void)n_in; (void)out_size;
    const float* x    = (const float*)d_in[0];
    const int*   ei   = (const int*)d_in[1];
    const float* ea   = (const float*)d_in[2];
    const float* Wl1  = (const float*)d_in[4];
    const float* bl1  = (const float*)d_in[5];
    const float* Wr1  = (const float*)d_in[6];
    const float* br1  = (const float*)d_in[7];
    const float* Wl2  = (const float*)d_in[8];
    const float* bl2  = (const float*)d_in[9];
    const float* Wr2  = (const float*)d_in[10];
    const float* br2  = (const float*)d_in[11];
    const float* Wg1  = (const float*)d_in[12];
    const float* bg1  = (const float*)d_in[13];
    const float* Wrel = (const float*)d_in[14];
    const float* brel = (const float*)d_in[15];
    const float* Wroot= (const float*)d_in[16];
    const float* Wc0  = (const float*)d_in[17];
    const float* Wc1  = (const float*)d_in[18];
    const float* Wc2  = (const float*)d_in[19];
    const float* bc   = (const float*)d_in[20];

    mm1_kernel<<<25, 256>>>(x, Wl1, Wr1);

    size_t smem = sizeof(SM);
    cudaFuncSetAttribute(brain_kernel, cudaFuncAttributeMaxDynamicSharedMemorySize, (int)smem);
    brain_kernel<<<1, NT, smem>>>(ei, ea, bl1, br1, Wl2, bl2, Wr2, br2,
                                  Wg1, bg1, Wrel, brel, Wroot, Wc0, Wc1, Wc2, bc,
                                  (float*)d_out);
}

// round 3
// speedup vs baseline: 2.0841x; 1.2490x over previous
#include <cuda_runtime.h>

#define NT 1024
#define NEDGE 2000

__device__ float g_xwl[6400];
__device__ float g_xwr[6400];

struct __align__(16) SM {
    float  bigA[10000];   // u16 cnt[100*100] (first 5000 floats) -> xw2l|xw2r|h2p|xw3|tmp
    float  bigB[8000];    // src|dst|ew|col -> Tx1|Lh2|ass
    float  bigC[3400];    // pooled(1000)|Hc(400)|s2(2000)
    float  h1[6400];
    float  h2[2000];
    float  csr_w[2000];
    int    csr_src[2000];
    int    csr_dst[2000];
    float2 pl[2000];      // (coeff, src) packed; later (ccheb, rs*20)
    float2 pr[2000];
    float2 pg[2000];
    float  wbuf[4160];    // WL2|WR2|WG1|WC0|WC1|WC2
    int    rowptr[104];
    int    scanbuf[128];
    float  dis_l[100], dis_r[100], dis_g[100], dis_c[100];
    float  score[100], tanhv[64], qv[100], qr[100];
    int    node_idx[100], perm[64], ks[64];
    int    flag64;
};

__device__ __forceinline__ float lrelu(float v) { return v > 0.f ? v : 0.01f * v; }
__device__ __forceinline__ float4 lrelu4(float4 v) {
    return make_float4(lrelu(v.x), lrelu(v.y), lrelu(v.z), lrelu(v.w));
}

// ---------------- K1: layer-1 matmuls across 25 SMs ----------------
__global__ __launch_bounds__(256, 1) void mm1_kernel(
    const float* __restrict__ x,
    const float* __restrict__ Wl1, const float* __restrict__ Wr1)
{
    __shared__ float xs[400];
    const int b = blockIdx.x, tid = threadIdx.x;
    for (int i = tid; i < 400; i += 256) xs[i] = x[b * 400 + i];
    __syncthreads();
    const int j = tid & 63, r = tid >> 6;
    float al = 0.f, ar = 0.f;
    for (int k = 0; k < 100; k++) {
        float xv = xs[r * 100 + k];
        al += xv * __ldg(&Wl1[k * 64 + j]);
        ar += xv * __ldg(&Wr1[k * 64 + j]);
    }
    const int row = b * 4 + r;
    g_xwl[row * 64 + j] = al;
    g_xwr[row * 64 + j] = ar;
}

// ---------------- K2: everything else, one block, 1024 threads ----------------
__global__ __launch_bounds__(NT, 1) void brain_kernel(
    const int* __restrict__ ei32, const float* __restrict__ ea,
    const float* __restrict__ bl1, const float* __restrict__ br1,
    const float* __restrict__ Wl2, const float* __restrict__ bl2,
    const float* __restrict__ Wr2, const float* __restrict__ br2,
    const float* __restrict__ Wg1, const float* __restrict__ bg1,
    const float* __restrict__ Wrel, const float* __restrict__ brel,
    const float* __restrict__ Wroot,
    const float* __restrict__ Wc0, const float* __restrict__ Wc1,
    const float* __restrict__ Wc2, const float* __restrict__ bc,
    float* __restrict__ out)
{
    extern __shared__ char raw[];
    SM* S = (SM*)raw;
    const int tid = threadIdx.x;

    int*   srcA = (int*)S->bigB;
    int*   dstA = srcA + 2000;
    float* ewA  = S->bigB + 4000;
    int*   colA = srcA + 6000;
    float* WL2 = S->wbuf;
    float* WR2 = S->wbuf + 1280;
    float* WG1 = S->wbuf + 2560;
    float* WC0 = S->wbuf + 2960;
    float* WC1 = S->wbuf + 3360;
    float* WC2 = S->wbuf + 3760;

    // ---- P0: probe dtype, load edges/weights, zero cnt ----
    if (tid == 0) S->flag64 = 0;
    if (tid < 128) S->scanbuf[tid] = 0;
    __syncthreads();
    if (tid < 100 && ei32[2 * tid + 1] != 0) atomicOr(&S->flag64, 1);
    for (int e = tid; e < NEDGE; e += NT) ewA[e] = ea[e];
    for (int i = tid; i < 1280; i += NT) { WL2[i] = Wl2[i]; WR2[i] = Wr2[i]; }
    for (int i = tid; i < 400; i += NT) {
        WG1[i] = Wg1[i]; WC0[i] = Wc0[i]; WC1[i] = Wc1[i]; WC2[i] = Wc2[i];
    }
    {
        unsigned* z = (unsigned*)S->bigA;
        for (int i = tid; i < 5000; i += NT) z[i] = 0;
    }
    __syncthreads();
    if (S->flag64 == 0) {
        const long long* ei = (const long long*)ei32;
        for (int e = tid; e < NEDGE; e += NT) {
            srcA[e] = (int)ei[e];
            dstA[e] = (int)ei[NEDGE + e];
        }
    } else {
        for (int e = tid; e < NEDGE; e += NT) {
            srcA[e] = ei32[e];
            dstA[e] = ei32[NEDGE + e];
        }
    }
    __syncthreads();

    // ---- P1: stable CSR by dst (u16 counting sort, deterministic) ----
    unsigned short* cnt = (unsigned short*)S->bigA;
    if (tid < 100) {
        unsigned short* row = cnt + tid * 100;
        const int e0 = tid * 20;
        #pragma unroll
        for (int e = e0; e < e0 + 20; e++) row[dstA[e]]++;
    }
    __syncthreads();
    if (tid < 100) {
        int s = 0;
        for (int t = 0; t < 100; t++) {
            int v = cnt[t * 100 + tid];
            cnt[t * 100 + tid] = (unsigned short)s;
            s += v;
        }
        S->scanbuf[tid] = s;
    }
    __syncthreads();
    if (tid < 32) {   // warp-level inclusive scan of 128 entries
        const int base = tid * 4;
        int a0 = S->scanbuf[base], a1 = S->scanbuf[base + 1];
        int a2 = S->scanbuf[base + 2], a3 = S->scanbuf[base + 3];
        a1 += a0; a2 += a1; a3 += a2;
        int s = a3;
        #pragma unroll
        for (int off = 1; off < 32; off <<= 1) {
            int n = __shfl_up_sync(0xffffffffu, s, off);
            if (tid >= off) s += n;
        }
        int bs = s - a3;
        S->scanbuf[base] = bs + a0; S->scanbuf[base + 1] = bs + a1;
        S->scanbuf[base + 2] = bs + a2; S->scanbuf[base + 3] = bs + a3;
    }
    __syncthreads();
    if (tid < 100) S->rowptr[tid + 1] = S->scanbuf[tid];
    if (tid == 0) S->rowptr[0] = 0;
    __syncthreads();
    if (tid < 100) {
        unsigned short* row = cnt + tid * 100;
        const int e0 = tid * 20;
        for (int e = e0; e < e0 + 20; e++) {
            int d = dstA[e];
            colA[S->rowptr[d] + row[d]] = e;
            row[d]++;
        }
    }
    __syncthreads();

    // ---- P1.5: gather to CSR order ----
    for (int p = tid; p < NEDGE; p += NT) {
        int e = colA[p];
        S->csr_src[p] = srcA[e];
        S->csr_dst[p] = dstA[e];
        S->csr_w[p]   = ewA[e];
    }
    __syncthreads();

    // ---- P2: degrees + packed coefficients ----
    if (tid < 100) {
        float dl = 0.f, dr = 0.f, dg = 0.f;
        const int d = tid;
        for (int p = S->rowptr[d]; p < S->rowptr[d + 1]; p++) {
            int s = S->csr_src[p]; float w = S->csr_w[p];
            dg += w;
            if (d < 50 && s < 50)   dl += w;
            if (d >= 50 && s >= 50) dr += w;
        }
        S->dis_l[d] = rsqrtf(dl + 1.f);
        S->dis_r[d] = rsqrtf(dr + 1.f);
        S->dis_g[d] = rsqrtf(dg + 1.f);
    }
    __syncthreads();
    for (int p = tid; p < NEDGE; p += NT) {
        int s = S->csr_src[p], d = S->csr_dst[p]; float w = S->csr_w[p];
        float cl = (s < 50 && d < 50)   ? S->dis_l[s] * w * S->dis_l[d] : 0.f;
        float cr = (s >= 50 && d >= 50) ? S->dis_r[s] * w * S->dis_r[d] : 0.f;
        float cg = S->dis_g[s] * w * S->dis_g[d];
        float fs = __int_as_float(s);
        S->pl[p] = make_float2(cl, fs);
        S->pr[p] = make_float2(cr, fs);
        S->pg[p] = make_float2(cg, fs);
    }
    __syncthreads();

    // ---- P4: layer-1 GCN aggregate (xw from global, float4) -> h1 ----
    for (int idx = tid; idx < 1600; idx += NT) {
        const int i = idx >> 4, f0 = (idx & 15) << 2;
        const float* gx; const float2* pp; float di; const float* bias;
        if (i < 50) { gx = g_xwl; pp = S->pl; di = S->dis_l[i]; bias = bl1; }
        else        { gx = g_xwr; pp = S->pr; di = S->dis_r[i]; bias = br1; }
        float4 sv = __ldg((const float4*)(gx + i * 64 + f0));
        float4 b4 = __ldg((const float4*)(bias + f0));
        float dd = di * di;
        float4 acc = make_float4(dd * sv.x + b4.x, dd * sv.y + b4.y,
                                 dd * sv.z + b4.z, dd * sv.w + b4.w);
        for (int p = S->rowptr[i]; p < S->rowptr[i + 1]; p++) {
            float2 cs = pp[p];
            int s = __float_as_int(cs.y);
            float4 v = __ldg((const float4*)(gx + s * 64 + f0));
            acc.x += cs.x * v.x; acc.y += cs.x * v.y;
            acc.z += cs.x * v.z; acc.w += cs.x * v.w;
        }
        *(float4*)&S->h1[i * 64 + f0] = lrelu4(acc);
    }
    __syncthreads();

    float* xw2l = S->bigA;
    float* xw2r = S->bigA + 2000;
    float* h2p  = S->bigA + 4000;
    float* xw3  = S->bigA + 6000;
    float* tmp  = S->bigA + 8000;

    // ---- P5: layer-2 matmuls (smem weights, float4 h1, float2 weights) ----
    if (tid < 1000) {
        const int i = tid / 10, f0 = (tid % 10) * 2;
        float al0 = 0.f, al1 = 0.f, ar0 = 0.f, ar1 = 0.f;
        for (int k0 = 0; k0 < 64; k0 += 4) {
            float4 hv = *(const float4*)&S->h1[i * 64 + k0];
            {
                float2 wl = *(const float2*)&WL2[(k0 + 0) * 20 + f0];
                float2 wr = *(const float2*)&WR2[(k0 + 0) * 20 + f0];
                al0 += hv.x * wl.x; al1 += hv.x * wl.y;
                ar0 += hv.x * wr.x; ar1 += hv.x * wr.y;
            }
            {
                float2 wl = *(const float2*)&WL2[(k0 + 1) * 20 + f0];
                float2 wr = *(const float2*)&WR2[(k0 + 1) * 20 + f0];
                al0 += hv.y * wl.x; al1 += hv.y * wl.y;
                ar0 += hv.y * wr.x; ar1 += hv.y * wr.y;
            }
            {
                float2 wl = *(const float2*)&WL2[(k0 + 2) * 20 + f0];
                float2 wr = *(const float2*)&WR2[(k0 + 2) * 20 + f0];
                al0 += hv.z * wl.x; al1 += hv.z * wl.y;
                ar0 += hv.z * wr.x; ar1 += hv.z * wr.y;
            }
            {
                float2 wl = *(const float2*)&WL2[(k0 + 3) * 20 + f0];
                float2 wr = *(const float2*)&WR2[(k0 + 3) * 20 + f0];
                al0 += hv.w * wl.x; al1 += hv.w * wl.y;
                ar0 += hv.w * wr.x; ar1 += hv.w * wr.y;
            }
        }
        xw2l[i * 20 + f0] = al0; xw2l[i * 20 + f0 + 1] = al1;
        xw2r[i * 20 + f0] = ar0; xw2r[i * 20 + f0 + 1] = ar1;
    }
    __syncthreads();

    // ---- P6: layer-2 GCN aggregate ----
    if (tid < 500) {
        const int i = tid / 5, f0 = (tid % 5) * 4;
        const float* xw; const float2* pp; float di; const float* bias;
        if (i < 50) { xw = xw2l; pp = S->pl; di = S->dis_l[i]; bias = bl2; }
        else        { xw = xw2r; pp = S->pr; di = S->dis_r[i]; bias = br2; }
        float4 sv = *(const float4*)&xw[i * 20 + f0];
        float4 b4 = __ldg((const float4*)(bias + f0));
        float dd = di * di;
        float4 acc = make_float4(dd * sv.x + b4.x, dd * sv.y + b4.y,
                                 dd * sv.z + b4.z, dd * sv.w + b4.w);
        for (int p = S->rowptr[i]; p < S->rowptr[i + 1]; p++) {
            float2 cs = pp[p];
            int s = __float_as_int(cs.y);
            float4 v = *(const float4*)&xw[s * 20 + f0];
            acc.x += cs.x * v.x; acc.y += cs.x * v.y;
            acc.z += cs.x * v.z; acc.w += cs.x * v.w;
        }
        *(float4*)&h2p[i * 20 + f0] = lrelu4(acc);
    }
    __syncthreads();

    // ---- P7: layer-3 dense matmul then global aggregate -> h2 ----
    if (tid < 500) {
        const int i = tid / 5, f0 = (tid % 5) * 4;
        float4 acc = make_float4(0.f, 0.f, 0.f, 0.f);
        for (int k = 0; k < 20; k++) {
            float hv = h2p[i * 20 + k];
            float4 w = *(const float4*)&WG1[k * 20 + f0];
            acc.x += hv * w.x; acc.y += hv * w.y; acc.z += hv * w.z; acc.w += hv * w.w;
        }
        *(float4*)&xw3[i * 20 + f0] = acc;
    }
    __syncthreads();
    if (tid < 500) {
        const int i = tid / 5, f0 = (tid % 5) * 4;
        float di = S->dis_g[i], dd = di * di;
        float4 sv = *(const float4*)&xw3[i * 20 + f0];
        float4 b4 = __ldg((const float4*)(bg1 + f0));
        float4 acc = make_float4(dd * sv.x + b4.x, dd * sv.y + b4.y,
                                 dd * sv.z + b4.z, dd * sv.w + b4.w);
        for (int p = S->rowptr[i]; p < S->rowptr[i + 1]; p++) {
            float2 cs = S->pg[p];
            int s = __float_as_int(cs.y);
            float4 v = *(const float4*)&xw3[s * 20 + f0];
            acc.x += cs.x * v.x; acc.y += cs.x * v.y;
            acc.z += cs.x * v.z; acc.w += cs.x * v.w;
        }
        *(float4*)&S->h2[i * 20 + f0] = lrelu4(acc);
    }
    __syncthreads();

    // ---- P8: SAGPool score via per-node scalars ----
    if (tid < 100) {
        float q = 0.f, qq = 0.f;
        for (int f0 = 0; f0 < 20; f0 += 4) {
            float4 h = *(const float4*)&S->h2[tid * 20 + f0];
            float4 a = __ldg((const float4*)(Wrel + f0));
            float4 b = __ldg((const float4*)(Wroot + f0));
            q  += h.x * a.x + h.y * a.y + h.z * a.z + h.w * a.w;
            qq += h.x * b.x + h.y * b.y + h.z * b.z + h.w * b.w;
        }
        S->qv[tid] = q; S->qr[tid] = qq;
    }
    __syncthreads();
    if (tid < 100) {
        float s = __ldg(&brel[0]) + S->qr[tid];
        for (int p = S->rowptr[tid]; p < S->rowptr[tid + 1]; p++)
            s += S->qv[S->csr_src[p]];
        S->score[tid] = s;
    }
    __syncthreads();

    // ---- P9: top-k(50) rank counting ----
    if (tid < 100) {
        float si = S->score[tid];
        int r = 0;
        for (int j = 0; j < 100; j++) {
            float sj = S->score[j];
            if (sj > si || (sj == si && j < tid)) r++;
        }
        S->node_idx[tid] = (r < 50) ? r : -1;
        if (r < 50) { S->perm[r] = tid; S->tanhv[r] = tanhf(si); }
    }
    __syncthreads();

    // ---- P10: ks, dis_c, pooled ----
    float* pooled = S->bigC;
    float* Hc     = S->bigC + 1000;
    float* s2     = S->bigC + 1400;
    if (tid < 100) {
        int r = S->node_idx[tid];
        if (r >= 0) {
            int pos = 0;
            for (int j = 0; j < tid; j++) if (S->node_idx[j] >= 0) pos++;
            S->ks[pos] = tid;
            float d = 0.f;
            for (int p = S->rowptr[tid]; p < S->rowptr[tid + 1]; p++)
                if (S->node_idx[S->csr_src[p]] >= 0) d += 1.f;
            S->dis_c[r] = (d > 0.f) ? rsqrtf(d) : 0.f;
        }
    } else if (tid >= 512 && tid < 762) {
        const int t = tid - 512;
        const int r = t / 5, f0 = (t % 5) * 4;
        float4 v = *(const float4*)&S->h2[S->perm[r] * 20 + f0];
        float tv = S->tanhv[r];
        *(float4*)&pooled[r * 20 + f0] =
            make_float4(v.x * tv, v.y * tv, v.z * tv, v.w * tv);
    }
    __syncthreads();

    // ---- P10.5: Cheb packed coeffs (overwrite pl) ----
    for (int p = tid; p < NEDGE; p += NT) {
        int rs = S->node_idx[S->csr_src[p]];
        int rd = S->node_idx[S->csr_dst[p]];
        float c = 0.f; int off = 0;
        if (rs >= 0 && rd >= 0) { c = -S->dis_c[rs] * S->dis_c[rd]; off = rs * 20; }
        S->pl[p] = make_float2(c, __int_as_float(off));
    }
    __syncthreads();

    // ---- P11: Tx1 = Lhat(h2); Lh2 = Lhat(Tx1) ----
    float* Tx1 = S->bigB;
    float* Lh2 = S->bigB + 2000;
    float* ass = S->bigB + 4000;
    {
        float4 z4 = make_float4(0.f, 0.f, 0.f, 0.f);
        if (tid < 250) {
            const int rr = tid / 5, f0 = (tid % 5) * 4;
            const int i = S->perm[rr];
            float4 acc = z4;
            for (int p = S->rowptr[i]; p < S->rowptr[i + 1]; p++) {
                float2 cs = S->pl[p];
                int off = __float_as_int(cs.y);
                float4 v = *(const float4*)&S->h2[off + f0];
                acc.x += cs.x * v.x; acc.y += cs.x * v.y;
                acc.z += cs.x * v.z; acc.w += cs.x * v.w;
            }
            *(float4*)&Tx1[rr * 20 + f0] = acc;
        } else if (tid < 500) {
            ((float4*)Tx1)[tid] = z4;          // rows 50..99
        } else if (tid < 750) {
            ((float4*)Lh2)[tid - 250] = z4;    // rows 50..99
        }
    }
    __syncthreads();
    if (tid < 250) {
        const int rr = tid / 5, f0 = (tid % 5) * 4;
        const int i = S->perm[rr];
        float4 acc = make_float4(0.f, 0.f, 0.f, 0.f);
        for (int p = S->rowptr[i]; p < S->rowptr[i + 1]; p++) {
            float2 cs = S->pl[p];
            int off = __float_as_int(cs.y);
            float4 v = *(const float4*)&Tx1[off + f0];
            acc.x += cs.x * v.x; acc.y += cs.x * v.y;
            acc.z += cs.x * v.z; acc.w += cs.x * v.w;
        }
        *(float4*)&Lh2[rr * 20 + f0] = acc;
    }
    __syncthreads();

    // ---- P12: s_raw ----
    if (tid < 500) {
        const int i = tid / 5, f0 = (tid % 5) * 4;
        float4 acc = __ldg((const float4*)(bc + f0));
        for (int k = 0; k < 20; k++) {
            float t0 = S->h2[i * 20 + k];
            float t1 = Tx1[i * 20 + k];
            float t2 = 2.f * Lh2[i * 20 + k] - t0;
            float4 w0 = *(const float4*)&WC0[k * 20 + f0];
            float4 w1 = *(const float4*)&WC1[k * 20 + f0];
            float4 w2 = *(const float4*)&WC2[k * 20 + f0];
            acc.x += t0 * w0.x + t1 * w1.x + t2 * w2.x;
            acc.y += t0 * w0.y + t1 * w1.y + t2 * w2.y;
            acc.z += t0 * w0.z + t1 * w1.z + t2 * w2.z;
            acc.w += t0 * w0.w + t1 * w1.w + t2 * w2.w;
        }
        *(float4*)&ass[i * 20 + f0] = acc;
    }
    __syncthreads();

    // ---- P13: double softmax ----
    for (int pass = 0; pass < 2; pass++) {
        if (tid < 500) {
            const int i = tid / 5, f0 = (tid % 5) * 4;
            float m = -1e30f;
            for (int k0 = 0; k0 < 20; k0 += 4) {
                float4 a = *(const float4*)&ass[i * 20 + k0];
                m = fmaxf(m, fmaxf(fmaxf(a.x, a.y), fmaxf(a.z, a.w)));
            }
            float4 v = *(const float4*)&ass[i * 20 + f0];
            *(float4*)&tmp[i * 20 + f0] =
                make_float4(expf(v.x - m), expf(v.y - m), expf(v.z - m), expf(v.w - m));
        }
        __syncthreads();
        if (tid < 500) {
            const int i = tid / 5, f0 = (tid % 5) * 4;
            float s = 0.f;
            for (int k0 = 0; k0 < 20; k0 += 4) {
                float4 t = *(const float4*)&tmp[i * 20 + k0];
                s += t.x + t.y + t.z + t.w;
            }
            float inv = 1.f / s;
            float4 t = *(const float4*)&tmp[i * 20 + f0];
            float4 o = make_float4(t.x * inv, t.y * inv, t.z * inv, t.w * inv);
            if (pass == 0) *(float4*)&ass[i * 20 + f0] = o;
            else           *(float4*)&s2[i * 20 + f0]  = o;
        }
        __syncthreads();
    }

    // ---- P14: H_coarse = s2^T @ h2 (split-i partials) ----
    if (tid < 200) {
        const int c = tid / 10, rem = tid % 10;
        const int f0 = (rem % 5) * 4, half = rem / 5;
        float4 acc = make_float4(0.f, 0.f, 0.f, 0.f);
        for (int i = half * 50; i < half * 50 + 50; i++) {
            float sv = s2[i * 20 + c];
            float4 h = *(const float4*)&S->h2[i * 20 + f0];
            acc.x += sv * h.x; acc.y += sv * h.y; acc.z += sv * h.z; acc.w += sv * h.w;
        }
        ((float4*)tmp)[tid] = acc;
    }
    __syncthreads();
    if (tid < 100) {
        const int c = tid / 5, fp = tid % 5;
        float4 a = ((float4*)tmp)[c * 10 + fp];
        float4 b = ((float4*)tmp)[c * 10 + 5 + fp];
        *(float4*)&Hc[c * 20 + fp * 4] =
            make_float4(a.x + b.x, a.y + b.y, a.z + b.z, a.w + b.w);
    }
    __syncthreads();

    // ---- P15: out = pooled + ass[ks] @ H_coarse ----
    if (tid < 250) {
        const int j = tid / 5, f0 = (tid % 5) * 4;
        float4 acc = *(const float4*)&pooled[j * 20 + f0];
        const int row = S->ks[j];
        for (int k = 0; k < 20; k++) {
            float a = ass[row * 20 + k];
            float4 h = *(const float4*)&Hc[k * 20 + f0];
            acc.x += a * h.x; acc.y += a * h.y; acc.z += a * h.z; acc.w += a * h.w;
        }
        *(float4*)&out[j * 20 + f0] = acc;
    }
}

extern "C" void kernel_launch(void* const* d_in, const int* in_sizes, int n_in,
                              void* d_out, int out_size)
{
    (void)in_sizes; (void)n_in; (void)out_size;
    const float* x    = (const float*)d_in[0];
    const int*   ei   = (const int*)d_in[1];
    const float* ea   = (const float*)d_in[2];
    const float* Wl1  = (const float*)d_in[4];
    const float* bl1  = (const float*)d_in[5];
    const float* Wr1  = (const float*)d_in[6];
    const float* br1  = (const float*)d_in[7];
    const float* Wl2  = (const float*)d_in[8];
    const float* bl2  = (const float*)d_in[9];
    const float* Wr2  = (const float*)d_in[10];
    const float* br2  = (const float*)d_in[11];
    const float* Wg1  = (const float*)d_in[12];
    const float* bg1  = (const float*)d_in[13];
    const float* Wrel = (const float*)d_in[14];
    const float* brel = (const float*)d_in[15];
    const float* Wroot= (const float*)d_in[16];
    const float* Wc0  = (const float*)d_in[17];
    const float* Wc1  = (const float*)d_in[18];
    const float* Wc2  = (const float*)d_in[19];
    const float* bc   = (const float*)d_in[20];

    mm1_kernel<<<25, 256>>>(x, Wl1, Wr1);

    size_t smem = sizeof(SM);
    cudaFuncSetAttribute(brain_kernel, cudaFuncAttributeMaxDynamicSharedMemorySize, (int)smem);
    brain_kernel<<<1, NT, smem>>>(ei, ea, bl1, br1, Wl2, bl2, Wr2, br2,
                                  Wg1, bg1, Wrel, brel, Wroot, Wc0, Wc1, Wc2, bc,
                                  (float*)d_out);
}